// round 14
// baseline (speedup 1.0000x reference)
#include <cuda_runtime.h>
#include <cuda_fp16.h>
#include <math.h>
#include <stdint.h>

#define D 128
#define H 8
#define NMAX 100000
#define EMAX 1600000
#define RMAX 128
#define ALPHA 0.1f
#define SRCMASK 0xFFFFF

// ---------------- scratch (device globals; no allocations) ----------------
__device__ __half d_xnh[NMAX * D];     // LN(ent) fp16; later y = LN(rst) fp16
__device__ __half d_kqv[NMAX * 384];   // fused k|q|v fp16
__device__ float  d_rst[NMAX * D];     // rst = feat + ent (fp32)
__device__ __half d_fA[NMAX * D];
__device__ __half d_fB[NMAX * D];
__device__ __half d_exh[EMAX * H];
__device__ float  d_nscale[NMAX * H];
__device__ __half d_relxh[RMAX * D];
__device__ float  d_relp[RMAX * D];
__device__ __half d_w16[4 * 16384 + 2 * 65536];
__device__ int    d_deg[NMAX];
__device__ int    d_rowoff[NMAX];
__device__ int    d_cursor[NMAX];
__device__ int    d_pk[EMAX];          // src | (rid<<20), CSR order
__device__ int    d_bsums[256];

#define OFF_WKQV 0
#define OFF_WR   49152
#define OFF_W1   65536
#define OFF_W2   131072

// ---------------- typed helpers ----------------
__device__ __forceinline__ float4 ld4(const float* p) { return *(const float4*)p; }
__device__ __forceinline__ float4 ld4(const __half* p) {
    float2 r = *(const float2*)p;
    __half2 h0 = ((const __half2*)&r)[0];
    __half2 h1 = ((const __half2*)&r)[1];
    float2 a = __half22float2(h0), b = __half22float2(h1);
    return make_float4(a.x, a.y, b.x, b.y);
}
__device__ __forceinline__ void st2(float* p, float a, float b) {
    *(float2*)p = make_float2(a, b);
}
__device__ __forceinline__ void st2(__half* p, float a, float b) {
    *(__half2*)p = __floats2half2_rn(a, b);
}
__device__ __forceinline__ uint32_t smem_u32(const void* p) {
    return (uint32_t)__cvta_generic_to_shared(p);
}
__device__ __forceinline__ void cp_async16(uint32_t dst, const void* src, bool pred) {
    int sz = pred ? 16 : 0;
    asm volatile("cp.async.cg.shared.global [%0], [%1], 16, %2;\n"
                 :: "r"(dst), "l"(src), "r"(sz));
}
__device__ __forceinline__ void ldsm4(uint32_t* r, uint32_t addr) {
    asm volatile("ldmatrix.sync.aligned.m8n8.x4.shared.b16 {%0,%1,%2,%3}, [%4];"
                 : "=r"(r[0]), "=r"(r[1]), "=r"(r[2]), "=r"(r[3]) : "r"(addr));
}
__device__ __forceinline__ void ldsm4t(uint32_t* r, uint32_t addr) {
    asm volatile("ldmatrix.sync.aligned.m8n8.x4.trans.shared.b16 {%0,%1,%2,%3}, [%4];"
                 : "=r"(r[0]), "=r"(r[1]), "=r"(r[2]), "=r"(r[3]) : "r"(addr));
}
__device__ __forceinline__ void mma_f16(float* c, const uint32_t* a, const uint32_t* b) {
    asm volatile(
        "mma.sync.aligned.m16n8k16.row.col.f32.f16.f16.f32 "
        "{%0,%1,%2,%3}, {%4,%5,%6,%7}, {%8,%9}, {%0,%1,%2,%3};\n"
        : "+f"(c[0]), "+f"(c[1]), "+f"(c[2]), "+f"(c[3])
        : "r"(a[0]), "r"(a[1]), "r"(a[2]), "r"(a[3]), "r"(b[0]), "r"(b[1]));
}

// B-tile XOR swizzle: 16B chunk c of k-row r stored at chunk c^(r&7), stride 128.
#define BSW(krow, nhalf) ((krow) * 128 + ((((nhalf) >> 3) ^ ((krow) & 7)) << 3))

// ---------------- weight convert: kqv cat + rel + W1 + W2 ----------------
__global__ void cvt_weights(const float* __restrict__ wh, const float* __restrict__ wt,
                            const float* __restrict__ we, const float* __restrict__ wr,
                            const float* __restrict__ w1, const float* __restrict__ w2,
                            __half* __restrict__ out) {
    int base = (blockIdx.x * blockDim.x + threadIdx.x) * 4;
    const float* src; long dst;
    if (base < 16384) {
        int k = base >> 7, c = base & 127;
        src = wh + base; dst = (long)k * 384 + c;
    } else if (base < 32768) {
        int i = base - 16384; int k = i >> 7, c = i & 127;
        src = wt + i; dst = (long)k * 384 + 128 + c;
    } else if (base < 49152) {
        int i = base - 32768; int k = i >> 7, c = i & 127;
        src = we + i; dst = (long)k * 384 + 256 + c;
    } else if (base < 65536) {
        src = wr + (base - 49152); dst = base;
    } else if (base < 131072) {
        src = w1 + (base - 65536); dst = base;
    } else {
        src = w2 + (base - 131072); dst = base;
    }
    float4 v = *(const float4*)src;
    __half2* o = (__half2*)(out + dst);
    o[0] = __floats2half2_rn(v.x, v.y);
    o[1] = __floats2half2_rn(v.z, v.w);
}

// ---------------- CSR build ----------------
__global__ void hist_kernel(const int* __restrict__ dst, int* deg, int E) {
    int e = blockIdx.x * blockDim.x + threadIdx.x;
    if (e < E) atomicAdd(&deg[dst[e]], 1);
}

__global__ void scan1_kernel(const int* __restrict__ deg, int* rowoff, int* bsums, int n) {
    __shared__ int sh[1024];
    int i = blockIdx.x * 1024 + threadIdx.x;
    int v = (i < n) ? deg[i] : 0;
    sh[threadIdx.x] = v;
    __syncthreads();
    for (int off = 1; off < 1024; off <<= 1) {
        int t = (threadIdx.x >= off) ? sh[threadIdx.x - off] : 0;
        __syncthreads();
        sh[threadIdx.x] += t;
        __syncthreads();
    }
    if (i < n) rowoff[i] = sh[threadIdx.x] - v;  // exclusive
    if (threadIdx.x == 1023) bsums[blockIdx.x] = sh[1023];
}

__global__ void scan2_kernel(int* bsums, int nb) {
    __shared__ int sh[256];
    int v = (threadIdx.x < nb) ? bsums[threadIdx.x] : 0;
    sh[threadIdx.x] = v;
    __syncthreads();
    for (int off = 1; off < 256; off <<= 1) {
        int t = (threadIdx.x >= off) ? sh[threadIdx.x - off] : 0;
        __syncthreads();
        sh[threadIdx.x] += t;
        __syncthreads();
    }
    if (threadIdx.x < nb) bsums[threadIdx.x] = sh[threadIdx.x] - v;  // exclusive
}

__global__ void scan3_kernel(int* rowoff, int* cursor, const int* __restrict__ bsums, int n) {
    int i = blockIdx.x * blockDim.x + threadIdx.x;
    if (i < n) {
        int r = rowoff[i] + bsums[i >> 10];
        rowoff[i] = r;
        cursor[i] = r;
    }
}

__global__ void scatter_kernel(const int* __restrict__ src, const int* __restrict__ dst,
                               const int* __restrict__ rid, int* cursor, int* pk, int E) {
    int e = blockIdx.x * blockDim.x + threadIdx.x;
    if (e < E) {
        int p = atomicAdd(&cursor[dst[e]], 1);
        pk[p] = src[e] | (rid[e] << 20);
    }
}

// ---------------- layernorm (warp per row) ----------------
template<typename Tout>
__global__ void ln_kernel(const float* __restrict__ x, const float* __restrict__ g,
                          const float* __restrict__ b, Tout* __restrict__ y, int nrows) {
    int w = (blockIdx.x * blockDim.x + threadIdx.x) >> 5;
    if (w >= nrows) return;
    int lane = threadIdx.x & 31;
    float4 v = *(const float4*)(x + (long)w * D + lane * 4);
    float s = v.x + v.y + v.z + v.w;
    #pragma unroll
    for (int o = 16; o; o >>= 1) s += __shfl_xor_sync(0xffffffffu, s, o);
    float mean = s * (1.0f / 128.0f);
    float dx = v.x - mean, dy = v.y - mean, dz = v.z - mean, dw = v.w - mean;
    float q = dx * dx + dy * dy + dz * dz + dw * dw;
    #pragma unroll
    for (int o = 16; o; o >>= 1) q += __shfl_xor_sync(0xffffffffu, q, o);
    float inv = rsqrtf(q * (1.0f / 128.0f) + 1e-5f);
    float4 g4 = *(const float4*)(g + lane * 4);
    float4 b4 = *(const float4*)(b + lane * 4);
    st2(y + (long)w * D + lane * 4,     dx * inv * g4.x + b4.x, dy * inv * g4.y + b4.y);
    st2(y + (long)w * D + lane * 4 + 2, dz * inv * g4.z + b4.z, dw * inv * g4.w + b4.w);
}

// ---------------- single-shot fp16 GEMM, K=128 fixed ----------------
#define MS_STRIDE 136
#define MM1_SMEM ((128 * MS_STRIDE + 128 * 128) * 2)
template<typename Tout>
__global__ void __launch_bounds__(256, 2) mm1_f16_kernel(
    const __half* __restrict__ X, const __half* __restrict__ W,
    Tout* __restrict__ Y, int M, int Nc)
{
    extern __shared__ __half sm1[];
    __half* As = sm1;                    // 128 x 136
    __half* Bs = sm1 + 128 * MS_STRIDE;  // 128 x 128 swizzled
    const int tid = threadIdx.x;
    const int lane = tid & 31;
    const int warp = tid >> 5;
    const int m_off = (warp & 3) * 32;
    const int n_off = (warp >> 2) * 64;
    const int r0 = blockIdx.x * 128;
    const int n0 = blockIdx.y * 128;

    #pragma unroll
    for (int i = 0; i < 8; i++) {
        int ci = tid + i * 256;
        int r = ci >> 4, kc = (ci & 15) * 8;
        int gr = r0 + r;
        cp_async16(smem_u32(&As[r * MS_STRIDE + kc]), X + (long)gr * 128 + kc, gr < M);
        cp_async16(smem_u32(&Bs[BSW(r, kc)]), W + (long)r * Nc + n0 + kc, true);
    }
    asm volatile("cp.async.commit_group;\n" ::);

    float acc[2][8][4];
    #pragma unroll
    for (int mi = 0; mi < 2; mi++)
        #pragma unroll
        for (int ni = 0; ni < 8; ni++)
            #pragma unroll
            for (int j = 0; j < 4; j++) acc[mi][ni][j] = 0.0f;

    asm volatile("cp.async.wait_group 0;\n" ::);
    __syncthreads();

    #pragma unroll
    for (int ks = 0; ks < 8; ks++) {
        uint32_t a[2][4];
        #pragma unroll
        for (int mi = 0; mi < 2; mi++) {
            int m = m_off + mi * 16 + (lane & 7) + (lane & 8);
            int k = ks * 16 + ((lane >> 4) << 3);
            ldsm4(a[mi], smem_u32(&As[m * MS_STRIDE + k]));
        }
        uint32_t b[8][2];
        #pragma unroll
        for (int nb = 0; nb < 4; nb++) {
            uint32_t r[4];
            int k = ks * 16 + (lane & 7) + (lane & 8);
            int n = n_off + nb * 16 + ((lane >> 4) << 3);
            ldsm4t(r, smem_u32(&Bs[BSW(k, n)]));
            b[nb * 2][0] = r[0]; b[nb * 2][1] = r[1];
            b[nb * 2 + 1][0] = r[2]; b[nb * 2 + 1][1] = r[3];
        }
        #pragma unroll
        for (int mi = 0; mi < 2; mi++)
            #pragma unroll
            for (int ni = 0; ni < 8; ni++)
                mma_f16(acc[mi][ni], a[mi], b[ni]);
    }

    #pragma unroll
    for (int mi = 0; mi < 2; mi++) {
        #pragma unroll
        for (int half = 0; half < 2; half++) {
            int row = m_off + mi * 16 + (lane >> 2) + half * 8;
            int gr = r0 + row;
            if (gr >= M) continue;
            #pragma unroll
            for (int ni = 0; ni < 8; ni++) {
                int col = n_off + ni * 8 + (lane & 3) * 2;
                st2(Y + (long)gr * Nc + n0 + col,
                    acc[mi][ni][half * 2 + 0], acc[mi][ni][half * 2 + 1]);
            }
        }
    }
}

// ---------------- fused FFN: 128 threads, 64-row tile, 32x64 warp tiles ----------------
#define FS_STRIDE 136
#define FFN_SMEM ((2 * 64 * FS_STRIDE + 2 * 128 * 128) * 2)
__global__ void __launch_bounds__(128, 2) ffn_fused_kernel(
    const __half* __restrict__ Yh, const __half* __restrict__ W1,
    const __half* __restrict__ W2, const float* __restrict__ b1,
    const float* __restrict__ b2, const float* __restrict__ rst,
    float* __restrict__ out, int M)
{
    extern __shared__ __half fsm[];
    __half* As  = fsm;                                     // 64 x 136
    __half* Hs  = fsm + 64 * FS_STRIDE;                    // 64 x 136
    __half* Bs0 = fsm + 2 * 64 * FS_STRIDE;                // 128 x 128 swz
    __half* Bs1 = Bs0 + 128 * 128;                         // 128 x 128 swz
    const int tid = threadIdx.x;
    const int lane = tid & 31;
    const int warp = tid >> 5;             // 0..3
    const int m_off = (warp & 1) * 32;     // 2 x 2 grid of 32x64 warp tiles
    const int n_off = (warp >> 1) * 64;
    const int r0 = blockIdx.x * 64;

    auto load_w = [&](const __half* Wsrc, int row0, int col0, int ldw, __half* dstBs) {
        #pragma unroll
        for (int i = 0; i < 16; i++) {
            int ci = tid + i * 128;
            int r = ci >> 4, nc = (ci & 15) * 8;
            cp_async16(smem_u32(&dstBs[BSW(r, nc)]),
                       Wsrc + (long)(row0 + r) * ldw + col0 + nc, true);
        }
    };

    #pragma unroll
    for (int i = 0; i < 8; i++) {
        int ci = tid + i * 128;
        int r = ci >> 4, kc = (ci & 15) * 8;
        int gr = r0 + r;
        cp_async16(smem_u32(&As[r * FS_STRIDE + kc]), Yh + (long)gr * D + kc, gr < M);
    }
    load_w(W1, 0, 0, 512, Bs0);
    asm volatile("cp.async.commit_group;\n" ::);

    float acc2[2][8][4];
    #pragma unroll
    for (int mi = 0; mi < 2; mi++)
        #pragma unroll
        for (int ni = 0; ni < 8; ni++)
            #pragma unroll
            for (int j = 0; j < 4; j++) acc2[mi][ni][j] = 0.0f;

    auto gemm64 = [&](const __half* A, const __half* B, float acc[2][8][4]) {
        #pragma unroll
        for (int ks = 0; ks < 8; ks++) {
            uint32_t a[2][4];
            #pragma unroll
            for (int mi = 0; mi < 2; mi++) {
                int m = m_off + mi * 16 + (lane & 7) + (lane & 8);
                int k = ks * 16 + ((lane >> 4) << 3);
                ldsm4(a[mi], smem_u32(&A[m * FS_STRIDE + k]));
            }
            uint32_t b[8][2];
            #pragma unroll
            for (int nb = 0; nb < 4; nb++) {
                uint32_t r[4];
                int k = ks * 16 + (lane & 7) + (lane & 8);
                int n = n_off + nb * 16 + ((lane >> 4) << 3);
                ldsm4t(r, smem_u32(&B[BSW(k, n)]));
                b[nb * 2][0] = r[0]; b[nb * 2][1] = r[1];
                b[nb * 2 + 1][0] = r[2]; b[nb * 2 + 1][1] = r[3];
            }
            #pragma unroll
            for (int mi = 0; mi < 2; mi++)
                #pragma unroll
                for (int ni = 0; ni < 8; ni++)
                    mma_f16(acc[mi][ni], a[mi], b[ni]);
        }
    };

    for (int c = 0; c < 4; c++) {
        load_w(W2, c * 128, 0, 128, Bs1);
        asm volatile("cp.async.commit_group;\n" ::);
        asm volatile("cp.async.wait_group 1;\n" ::);
        __syncthreads();

        float accT[2][8][4];
        #pragma unroll
        for (int mi = 0; mi < 2; mi++)
            #pragma unroll
            for (int ni = 0; ni < 8; ni++)
                #pragma unroll
                for (int j = 0; j < 4; j++) accT[mi][ni][j] = 0.0f;
        gemm64(As, Bs0, accT);
        __syncthreads();

        if (c < 3) {
            load_w(W1, 0, (c + 1) * 128, 512, Bs0);
            asm volatile("cp.async.commit_group;\n" ::);
        }

        #pragma unroll
        for (int mi = 0; mi < 2; mi++) {
            #pragma unroll
            for (int half = 0; half < 2; half++) {
                int row = m_off + mi * 16 + (lane >> 2) + half * 8;
                #pragma unroll
                for (int ni = 0; ni < 8; ni++) {
                    int col = n_off + ni * 8 + (lane & 3) * 2;
                    float v0 = fmaxf(accT[mi][ni][half * 2 + 0] + b1[c * 128 + col], 0.0f);
                    float v1 = fmaxf(accT[mi][ni][half * 2 + 1] + b1[c * 128 + col + 1], 0.0f);
                    *(__half2*)(&Hs[row * FS_STRIDE + col]) = __floats2half2_rn(v0, v1);
                }
            }
        }
        if (c < 3) { asm volatile("cp.async.wait_group 1;\n" ::); }
        else       { asm volatile("cp.async.wait_group 0;\n" ::); }
        __syncthreads();

        gemm64(Hs, Bs1, acc2);
        __syncthreads();
    }

    #pragma unroll
    for (int mi = 0; mi < 2; mi++) {
        #pragma unroll
        for (int half = 0; half < 2; half++) {
            int row = m_off + mi * 16 + (lane >> 2) + half * 8;
            int gr = r0 + row;
            if (gr >= M) continue;
            #pragma unroll
            for (int ni = 0; ni < 8; ni++) {
                int col = n_off + ni * 8 + (lane & 3) * 2;
                float v0 = acc2[mi][ni][half * 2 + 0] + b2[col] + rst[(long)gr * D + col];
                float v1 = acc2[mi][ni][half * 2 + 1] + b2[col + 1] + rst[(long)gr * D + col + 1];
                st2(out + (long)gr * D + col, v0, v1);
            }
        }
    }
}

// ---------------- fused attention + hop1 (warp per dst node, pk pipelined) ----------------
__global__ void attn_hop1_kernel(const int* __restrict__ rowoff, const int* __restrict__ deg,
                                 const int* __restrict__ pk,
                                 const __half* __restrict__ kqv,
                                 const float* __restrict__ relp, __half* __restrict__ exh,
                                 float* __restrict__ nscale, __half* __restrict__ fA, int N) {
    int w = (blockIdx.x * blockDim.x + threadIdx.x) >> 5;
    if (w >= N) return;
    int lane = threadIdx.x & 31;
    int head4 = lane >> 2;
    int start = rowoff[w];
    int dg = deg[w];
    float4 q4 = ld4(kqv + (long)w * 384 + 128 + lane * 4);
    float c = log1pf((float)dg) * 0.25f;  // log_in / sqrt(DH)
    float sum = 0.0f;
    float4 acc = make_float4(0.f, 0.f, 0.f, 0.f);
    int pk0 = 0, pk1 = 0;
    if (dg > 0) {
        pk0 = pk[start];
        pk1 = pk[start + min(1, dg - 1)];
    }
    int i = 0;
    for (; i + 2 <= dg; i += 2) {
        // prefetch next pair's indices before touching the rows (clamped, branch-free)
        int pk2 = pk[start + min(i + 2, dg - 1)];
        int pk3 = pk[start + min(i + 3, dg - 1)];
        long s0 = (long)(pk0 & SRCMASK) * 384, s1 = (long)(pk1 & SRCMASK) * 384;
        float4 k0 = ld4(kqv + s0 + lane * 4);
        float4 k1 = ld4(kqv + s1 + lane * 4);
        float4 v0 = ld4(kqv + s0 + 256 + lane * 4);
        float4 v1 = ld4(kqv + s1 + 256 + lane * 4);
        float4 r0 = ld4(relp + (long)(pk0 >> 20) * D + lane * 4);
        float4 r1 = ld4(relp + (long)(pk1 >> 20) * D + lane * 4);
        float p0 = k0.x * r0.x * q4.x + k0.y * r0.y * q4.y + k0.z * r0.z * q4.z + k0.w * r0.w * q4.w;
        float p1 = k1.x * r1.x * q4.x + k1.y * r1.y * q4.y + k1.z * r1.z * q4.z + k1.w * r1.w * q4.w;
        p0 += __shfl_xor_sync(0xffffffffu, p0, 1);
        p1 += __shfl_xor_sync(0xffffffffu, p1, 1);
        p0 += __shfl_xor_sync(0xffffffffu, p0, 2);
        p1 += __shfl_xor_sync(0xffffffffu, p1, 2);
        float e0 = __expf(p0 * c);   // logits tiny: no max-subtraction needed
        float e1 = __expf(p1 * c);
        if ((lane & 3) == 0) {
            exh[(long)(start + i) * H + head4] = __float2half(e0);
            exh[(long)(start + i + 1) * H + head4] = __float2half(e1);
        }
        acc.x += e0 * v0.x + e1 * v1.x;
        acc.y += e0 * v0.y + e1 * v1.y;
        acc.z += e0 * v0.z + e1 * v1.z;
        acc.w += e0 * v0.w + e1 * v1.w;
        sum += e0 + e1;
        pk0 = pk2; pk1 = pk3;
    }
    if (i < dg) {
        long s0 = (long)(pk0 & SRCMASK) * 384;
        float4 k0 = ld4(kqv + s0 + lane * 4);
        float4 v0 = ld4(kqv + s0 + 256 + lane * 4);
        float4 r0 = ld4(relp + (long)(pk0 >> 20) * D + lane * 4);
        float p0 = k0.x * r0.x * q4.x + k0.y * r0.y * q4.y + k0.z * r0.z * q4.z + k0.w * r0.w * q4.w;
        p0 += __shfl_xor_sync(0xffffffffu, p0, 1);
        p0 += __shfl_xor_sync(0xffffffffu, p0, 2);
        float e0 = __expf(p0 * c);
        if ((lane & 3) == 0) exh[(long)(start + i) * H + head4] = __float2half(e0);
        acc.x += e0 * v0.x;
        acc.y += e0 * v0.y;
        acc.z += e0 * v0.z;
        acc.w += e0 * v0.w;
        sum += e0;
    }
    float sc = (sum > 0.0f) ? ((1.0f - ALPHA) / sum) : 0.0f;
    float4 z = ld4(kqv + (long)w * 384 + 256 + lane * 4);
    acc.x = acc.x * sc + ALPHA * z.x;
    acc.y = acc.y * sc + ALPHA * z.y;
    acc.z = acc.z * sc + ALPHA * z.z;
    acc.w = acc.w * sc + ALPHA * z.w;
    float2 pkd;
    ((__half2*)&pkd)[0] = __floats2half2_rn(acc.x, acc.y);
    ((__half2*)&pkd)[1] = __floats2half2_rn(acc.z, acc.w);
    *(float2*)(fA + (long)w * D + lane * 4) = pkd;
    float s_h = __shfl_sync(0xffffffffu, sum, (lane & 7) * 4);
    if (lane < 8)
        nscale[(long)w * H + lane] = (s_h > 0.0f) ? ((1.0f - ALPHA) / s_h) : 0.0f;
}

// ---------------- PPR diffusion hop (warp per dst node, pk/e pipelined) ----------------
__global__ void hop_kernel(const int* __restrict__ rowoff, const int* __restrict__ deg,
                           const int* __restrict__ pk, const __half* __restrict__ exh,
                           const float* __restrict__ nscale,
                           const __half* __restrict__ fin,
                           const __half* __restrict__ f0,
                           __half* __restrict__ fout, int N) {
    int w = (blockIdx.x * blockDim.x + threadIdx.x) >> 5;
    if (w >= N) return;
    int lane = threadIdx.x & 31;
    int head = lane >> 2;
    int start = rowoff[w];
    int dg = deg[w];
    float4 acc = make_float4(0.f, 0.f, 0.f, 0.f);
    int pk0 = 0, pk1 = 0;
    float e0 = 0.f, e1 = 0.f;
    if (dg > 0) {
        int j1 = min(1, dg - 1);
        pk0 = pk[start];
        pk1 = pk[start + j1];
        e0 = __half2float(exh[(long)start * H + head]);
        e1 = __half2float(exh[(long)(start + j1) * H + head]);
    }
    int i = 0;
    for (; i + 2 <= dg; i += 2) {
        int j2 = min(i + 2, dg - 1), j3 = min(i + 3, dg - 1);
        int pk2 = pk[start + j2];
        int pk3 = pk[start + j3];
        float e2 = __half2float(exh[(long)(start + j2) * H + head]);
        float e3 = __half2float(exh[(long)(start + j3) * H + head]);
        float4 fa = ld4(fin + (long)(pk0 & SRCMASK) * D + lane * 4);
        float4 fb = ld4(fin + (long)(pk1 & SRCMASK) * D + lane * 4);
        acc.x += e0 * fa.x + e1 * fb.x;
        acc.y += e0 * fa.y + e1 * fb.y;
        acc.z += e0 * fa.z + e1 * fb.z;
        acc.w += e0 * fa.w + e1 * fb.w;
        pk0 = pk2; pk1 = pk3; e0 = e2; e1 = e3;
    }
    if (i < dg) {
        float4 fa = ld4(fin + (long)(pk0 & SRCMASK) * D + lane * 4);
        acc.x += e0 * fa.x;
        acc.y += e0 * fa.y;
        acc.z += e0 * fa.z;
        acc.w += e0 * fa.w;
    }
    float sc = nscale[(long)w * H + head];
    float4 z = ld4(f0 + (long)w * 384 + lane * 4);   // v inside kqv
    acc.x = acc.x * sc + ALPHA * z.x;
    acc.y = acc.y * sc + ALPHA * z.y;
    acc.z = acc.z * sc + ALPHA * z.z;
    acc.w = acc.w * sc + ALPHA * z.w;
    float2 pkd;
    ((__half2*)&pkd)[0] = __floats2half2_rn(acc.x, acc.y);
    ((__half2*)&pkd)[1] = __floats2half2_rn(acc.z, acc.w);
    *(float2*)(fout + (long)w * D + lane * 4) = pkd;
}

// ---------------- last hop fused with residual + LN (pipelined) ----------------
__global__ void hop_last_kernel(const int* __restrict__ rowoff, const int* __restrict__ deg,
                                const int* __restrict__ pk, const __half* __restrict__ exh,
                                const float* __restrict__ nscale,
                                const __half* __restrict__ fin, const __half* __restrict__ f0,
                                const float* __restrict__ ent,
                                const float* __restrict__ g, const float* __restrict__ b,
                                __half* __restrict__ y, float* __restrict__ rst, int N) {
    int w = (blockIdx.x * blockDim.x + threadIdx.x) >> 5;
    if (w >= N) return;
    int lane = threadIdx.x & 31;
    int head = lane >> 2;
    int start = rowoff[w];
    int dg = deg[w];
    float4 acc = make_float4(0.f, 0.f, 0.f, 0.f);
    int pk0 = 0, pk1 = 0;
    float e0 = 0.f, e1 = 0.f;
    if (dg > 0) {
        int j1 = min(1, dg - 1);
        pk0 = pk[start];
        pk1 = pk[start + j1];
        e0 = __half2float(exh[(long)start * H + head]);
        e1 = __half2float(exh[(long)(start + j1) * H + head]);
    }
    int i = 0;
    for (; i + 2 <= dg; i += 2) {
        int j2 = min(i + 2, dg - 1), j3 = min(i + 3, dg - 1);
        int pk2 = pk[start + j2];
        int pk3 = pk[start + j3];
        float e2 = __half2float(exh[(long)(start + j2) * H + head]);
        float e3 = __half2float(exh[(long)(start + j3) * H + head]);
        float4 fa = ld4(fin + (long)(pk0 & SRCMASK) * D + lane * 4);
        float4 fb = ld4(fin + (long)(pk1 & SRCMASK) * D + lane * 4);
        acc.x += e0 * fa.x + e1 * fb.x;
        acc.y += e0 * fa.y + e1 * fb.y;
        acc.z += e0 * fa.z + e1 * fb.z;
        acc.w += e0 * fa.w + e1 * fb.w;
        pk0 = pk2; pk1 = pk3; e0 = e2; e1 = e3;
    }
    if (i < dg) {
        float4 fa = ld4(fin + (long)(pk0 & SRCMASK) * D + lane * 4);
        acc.x += e0 * fa.x;
        acc.y += e0 * fa.y;
        acc.z += e0 * fa.z;
        acc.w += e0 * fa.w;
    }
    float sc = nscale[(long)w * H + head];
    float4 z = ld4(f0 + (long)w * 384 + lane * 4);
    float4 e4 = *(const float4*)(ent + (long)w * D + lane * 4);
    float4 v;
    v.x = acc.x * sc + ALPHA * z.x + e4.x;
    v.y = acc.y * sc + ALPHA * z.y + e4.y;
    v.z = acc.z * sc + ALPHA * z.z + e4.z;
    v.w = acc.w * sc + ALPHA * z.w + e4.w;
    *(float4*)(rst + (long)w * D + lane * 4) = v;
    float s = v.x + v.y + v.z + v.w;
    #pragma unroll
    for (int o = 16; o; o >>= 1) s += __shfl_xor_sync(0xffffffffu, s, o);
    float mean = s * (1.0f / 128.0f);
    float dx = v.x - mean, dy = v.y - mean, dz = v.z - mean, dw = v.w - mean;
    float q = dx * dx + dy * dy + dz * dz + dw * dw;
    #pragma unroll
    for (int o = 16; o; o >>= 1) q += __shfl_xor_sync(0xffffffffu, q, o);
    float inv = rsqrtf(q * (1.0f / 128.0f) + 1e-5f);
    float4 g4 = *(const float4*)(g + lane * 4);
    float4 b4 = *(const float4*)(b + lane * 4);
    st2(y + (long)w * D + lane * 4,     dx * inv * g4.x + b4.x, dy * inv * g4.y + b4.y);
    st2(y + (long)w * D + lane * 4 + 2, dz * inv * g4.z + b4.z, dw * inv * g4.w + b4.w);
}

// ---------------- launch ----------------
extern "C" void kernel_launch(void* const* d_in, const int* in_sizes, int n_in,
                              void* d_out, int out_size) {
    const float* ent    = (const float*)d_in[0];
    const float* relf   = (const float*)d_in[1];
    const float* W_head = (const float*)d_in[2];
    const float* W_tail = (const float*)d_in[3];
    const float* W_ent  = (const float*)d_in[4];
    const float* W_rel  = (const float*)d_in[5];
    const float* g_ent  = (const float*)d_in[6];
    const float* b_ent  = (const float*)d_in[7];
    const float* g_rel  = (const float*)d_in[8];
    const float* b_rel  = (const float*)d_in[9];
    const float* g_ff   = (const float*)d_in[10];
    const float* b_ff   = (const float*)d_in[11];
    const float* W1     = (const float*)d_in[12];
    const float* b1     = (const float*)d_in[13];
    const float* W2     = (const float*)d_in[14];
    const float* b2     = (const float*)d_in[15];
    const int*   src    = (const int*)d_in[16];
    const int*   dst    = (const int*)d_in[17];
    const int*   rid    = (const int*)d_in[18];
    float* out = (float*)d_out;

    int N = in_sizes[0] / D;
    int R = in_sizes[1] / D;
    int E = in_sizes[16];

    float *p_rst, *p_nscale, *p_relp;
    __half *p_xnh, *p_kqv, *p_fA, *p_fB, *p_exh, *p_relxh, *p_w16;
    int *p_deg, *p_rowoff, *p_cursor, *p_pk, *p_bsums;
    cudaGetSymbolAddress((void**)&p_xnh, d_xnh);
    cudaGetSymbolAddress((void**)&p_kqv, d_kqv);
    cudaGetSymbolAddress((void**)&p_rst, d_rst);
    cudaGetSymbolAddress((void**)&p_fA, d_fA);
    cudaGetSymbolAddress((void**)&p_fB, d_fB);
    cudaGetSymbolAddress((void**)&p_exh, d_exh);
    cudaGetSymbolAddress((void**)&p_nscale, d_nscale);
    cudaGetSymbolAddress((void**)&p_relxh, d_relxh);
    cudaGetSymbolAddress((void**)&p_relp, d_relp);
    cudaGetSymbolAddress((void**)&p_w16, d_w16);
    cudaGetSymbolAddress((void**)&p_deg, d_deg);
    cudaGetSymbolAddress((void**)&p_rowoff, d_rowoff);
    cudaGetSymbolAddress((void**)&p_cursor, d_cursor);
    cudaGetSymbolAddress((void**)&p_pk, d_pk);
    cudaGetSymbolAddress((void**)&p_bsums, d_bsums);

    cudaFuncSetAttribute(ffn_fused_kernel,
                         cudaFuncAttributeMaxDynamicSharedMemorySize, FFN_SMEM);
    cudaFuncSetAttribute((const void*)mm1_f16_kernel<__half>,
                         cudaFuncAttributeMaxDynamicSharedMemorySize, MM1_SMEM);
    cudaFuncSetAttribute((const void*)mm1_f16_kernel<float>,
                         cudaFuncAttributeMaxDynamicSharedMemorySize, MM1_SMEM);

    int nb = (N + 1023) / 1024;
    int mblocks = (N + 127) / 128;

    // fork: CSR + rel chain run on cudaStreamPerThread, parallel to kqv chain.
    // Events created fresh per call and intentionally leaked (few harness calls;
    // destroying mid-capture is illegal; DisableTiming events hold no device mem).
    cudaEvent_t ev_fork, ev_w, ev_join;
    cudaEventCreateWithFlags(&ev_fork, cudaEventDisableTiming);
    cudaEventCreateWithFlags(&ev_w, cudaEventDisableTiming);
    cudaEventCreateWithFlags(&ev_join, cudaEventDisableTiming);
    cudaStream_t s2 = cudaStreamPerThread;

    cudaEventRecord(ev_fork, 0);
    cudaStreamWaitEvent(s2, ev_fork, 0);

    // branch A (s2): CSR build
    cudaMemsetAsync(p_deg, 0, N * sizeof(int), s2);
    hist_kernel<<<(E + 255) / 256, 256, 0, s2>>>(dst, p_deg, E);
    scan1_kernel<<<nb, 1024, 0, s2>>>(p_deg, p_rowoff, p_bsums, N);
    scan2_kernel<<<1, 256, 0, s2>>>(p_bsums, nb);
    scan3_kernel<<<(N + 255) / 256, 256, 0, s2>>>(p_rowoff, p_cursor, p_bsums, N);
    scatter_kernel<<<(E + 255) / 256, 256, 0, s2>>>(src, dst, rid, p_cursor, p_pk, E);

    // branch B (main): weights + LN + kqv projection
    cvt_weights<<<192, 256>>>(W_head, W_tail, W_ent, W_rel, W1, W2, p_w16);
    cudaEventRecord(ev_w, 0);
    ln_kernel<__half><<<(N + 7) / 8, 256>>>(ent, g_ent, b_ent, p_xnh, N);
    mm1_f16_kernel<__half><<<dim3(mblocks, 3), 256, MM1_SMEM>>>(
        p_xnh, p_w16 + OFF_WKQV, p_kqv, N, 384);

    // branch A continues: rel chain (needs w16 from branch B); fp32 output
    cudaStreamWaitEvent(s2, ev_w, 0);
    ln_kernel<__half><<<(R + 7) / 8, 256, 0, s2>>>(relf, g_rel, b_rel, p_relxh, R);
    mm1_f16_kernel<float><<<dim3(1, 1), 256, MM1_SMEM, s2>>>(
        p_relxh, p_w16 + OFF_WR, p_relp, R, 128);
    cudaEventRecord(ev_join, s2);

    // join: attention needs both branches
    cudaStreamWaitEvent(0, ev_join, 0);

    // fused attention + hop1
    attn_hop1_kernel<<<(N + 7) / 8, 256>>>(p_rowoff, p_deg, p_pk, p_kqv,
                                           p_relp, p_exh, p_nscale, p_fA, N);

    // hops 2,3 then last fused with residual+LN
    hop_kernel<<<(N + 7) / 8, 256>>>(p_rowoff, p_deg, p_pk, p_exh, p_nscale,
                                     p_fA, p_kqv + 256, p_fB, N);
    hop_kernel<<<(N + 7) / 8, 256>>>(p_rowoff, p_deg, p_pk, p_exh, p_nscale,
                                     p_fB, p_kqv + 256, p_fA, N);
    hop_last_kernel<<<(N + 7) / 8, 256>>>(p_rowoff, p_deg, p_pk, p_exh, p_nscale,
                                          p_fA, p_kqv + 256, ent, g_ff, b_ff,
                                          p_xnh, p_rst, N);   // y -> d_xnh

    // fused FFN (128 threads, 64-row tile, 32x64 warp tiles, 2 blocks/SM)
    ffn_fused_kernel<<<(N + 63) / 64, 128, FFN_SMEM>>>(
        p_xnh, p_w16 + OFF_W1, p_w16 + OFF_W2, b1, b2, p_rst, out, N);
}

// round 15
// speedup vs baseline: 1.0712x; 1.0712x over previous
#include <cuda_runtime.h>
#include <cuda_fp16.h>
#include <math.h>
#include <stdint.h>

#define D 128
#define H 8
#define NMAX 100000
#define EMAX 1600000
#define RMAX 128
#define ALPHA 0.1f
#define SRCMASK 0xFFFFF

// ---------------- scratch (device globals; no allocations) ----------------
__device__ __half d_xnh[NMAX * D];     // LN(ent) fp16; later y = LN(rst) fp16
__device__ __half d_kqv[NMAX * 384];   // fused k|q|v fp16
__device__ float  d_rst[NMAX * D];     // rst = feat + ent (fp32)
__device__ __half d_fA[NMAX * D];
__device__ __half d_fB[NMAX * D];
__device__ __half d_exh[EMAX * H];
__device__ float  d_nscale[NMAX * H];
__device__ __half d_relxh[RMAX * D];
__device__ __half d_relph[RMAX * D];
__device__ __half d_w16[4 * 16384 + 2 * 65536];
__device__ int    d_deg[NMAX];
__device__ int    d_rowoff[NMAX];
__device__ int    d_cursor[NMAX];
__device__ int    d_pk[EMAX];          // src | (rid<<20), CSR order
__device__ int    d_bsums[256];

#define OFF_WKQV 0
#define OFF_WR   49152
#define OFF_W1   65536
#define OFF_W2   131072

// ---------------- typed helpers ----------------
__device__ __forceinline__ float4 ld4(const float* p) { return *(const float4*)p; }
__device__ __forceinline__ float4 ld4(const __half* p) {
    float2 r = *(const float2*)p;
    __half2 h0 = ((const __half2*)&r)[0];
    __half2 h1 = ((const __half2*)&r)[1];
    float2 a = __half22float2(h0), b = __half22float2(h1);
    return make_float4(a.x, a.y, b.x, b.y);
}
__device__ __forceinline__ void st2(float* p, float a, float b) {
    *(float2*)p = make_float2(a, b);
}
__device__ __forceinline__ void st2(__half* p, float a, float b) {
    *(__half2*)p = __floats2half2_rn(a, b);
}
__device__ __forceinline__ uint32_t smem_u32(const void* p) {
    return (uint32_t)__cvta_generic_to_shared(p);
}
__device__ __forceinline__ void cp_async16(uint32_t dst, const void* src, bool pred) {
    int sz = pred ? 16 : 0;
    asm volatile("cp.async.cg.shared.global [%0], [%1], 16, %2;\n"
                 :: "r"(dst), "l"(src), "r"(sz));
}
__device__ __forceinline__ void ldsm4(uint32_t* r, uint32_t addr) {
    asm volatile("ldmatrix.sync.aligned.m8n8.x4.shared.b16 {%0,%1,%2,%3}, [%4];"
                 : "=r"(r[0]), "=r"(r[1]), "=r"(r[2]), "=r"(r[3]) : "r"(addr));
}
__device__ __forceinline__ void ldsm4t(uint32_t* r, uint32_t addr) {
    asm volatile("ldmatrix.sync.aligned.m8n8.x4.trans.shared.b16 {%0,%1,%2,%3}, [%4];"
                 : "=r"(r[0]), "=r"(r[1]), "=r"(r[2]), "=r"(r[3]) : "r"(addr));
}
__device__ __forceinline__ void mma_f16(float* c, const uint32_t* a, const uint32_t* b) {
    asm volatile(
        "mma.sync.aligned.m16n8k16.row.col.f32.f16.f16.f32 "
        "{%0,%1,%2,%3}, {%4,%5,%6,%7}, {%8,%9}, {%0,%1,%2,%3};\n"
        : "+f"(c[0]), "+f"(c[1]), "+f"(c[2]), "+f"(c[3])
        : "r"(a[0]), "r"(a[1]), "r"(a[2]), "r"(a[3]), "r"(b[0]), "r"(b[1]));
}

// B-tile XOR swizzle: 16B chunk c of k-row r stored at chunk c^(r&7), stride 128.
#define BSW(krow, nhalf) ((krow) * 128 + ((((nhalf) >> 3) ^ ((krow) & 7)) << 3))

// ---------------- weight convert: kqv cat + rel + W1 + W2 ----------------
__global__ void cvt_weights(const float* __restrict__ wh, const float* __restrict__ wt,
                            const float* __restrict__ we, const float* __restrict__ wr,
                            const float* __restrict__ w1, const float* __restrict__ w2,
                            __half* __restrict__ out) {
    int base = (blockIdx.x * blockDim.x + threadIdx.x) * 4;
    const float* src; long dst;
    if (base < 16384) {
        int k = base >> 7, c = base & 127;
        src = wh + base; dst = (long)k * 384 + c;
    } else if (base < 32768) {
        int i = base - 16384; int k = i >> 7, c = i & 127;
        src = wt + i; dst = (long)k * 384 + 128 + c;
    } else if (base < 49152) {
        int i = base - 32768; int k = i >> 7, c = i & 127;
        src = we + i; dst = (long)k * 384 + 256 + c;
    } else if (base < 65536) {
        src = wr + (base - 49152); dst = base;
    } else if (base < 131072) {
        src = w1 + (base - 65536); dst = base;
    } else {
        src = w2 + (base - 131072); dst = base;
    }
    float4 v = *(const float4*)src;
    __half2* o = (__half2*)(out + dst);
    o[0] = __floats2half2_rn(v.x, v.y);
    o[1] = __floats2half2_rn(v.z, v.w);
}

// ---------------- CSR build ----------------
__global__ void hist_kernel(const int* __restrict__ dst, int* deg, int E) {
    int e = blockIdx.x * blockDim.x + threadIdx.x;
    if (e < E) atomicAdd(&deg[dst[e]], 1);
}

__global__ void scan1_kernel(const int* __restrict__ deg, int* rowoff, int* bsums, int n) {
    __shared__ int sh[1024];
    int i = blockIdx.x * 1024 + threadIdx.x;
    int v = (i < n) ? deg[i] : 0;
    sh[threadIdx.x] = v;
    __syncthreads();
    for (int off = 1; off < 1024; off <<= 1) {
        int t = (threadIdx.x >= off) ? sh[threadIdx.x - off] : 0;
        __syncthreads();
        sh[threadIdx.x] += t;
        __syncthreads();
    }
    if (i < n) rowoff[i] = sh[threadIdx.x] - v;  // exclusive
    if (threadIdx.x == 1023) bsums[blockIdx.x] = sh[1023];
}

__global__ void scan2_kernel(int* bsums, int nb) {
    __shared__ int sh[256];
    int v = (threadIdx.x < nb) ? bsums[threadIdx.x] : 0;
    sh[threadIdx.x] = v;
    __syncthreads();
    for (int off = 1; off < 256; off <<= 1) {
        int t = (threadIdx.x >= off) ? sh[threadIdx.x - off] : 0;
        __syncthreads();
        sh[threadIdx.x] += t;
        __syncthreads();
    }
    if (threadIdx.x < nb) bsums[threadIdx.x] = sh[threadIdx.x] - v;  // exclusive
}

__global__ void scan3_kernel(int* rowoff, int* cursor, const int* __restrict__ bsums, int n) {
    int i = blockIdx.x * blockDim.x + threadIdx.x;
    if (i < n) {
        int r = rowoff[i] + bsums[i >> 10];
        rowoff[i] = r;
        cursor[i] = r;
    }
}

__global__ void scatter_kernel(const int* __restrict__ src, const int* __restrict__ dst,
                               const int* __restrict__ rid, int* cursor, int* pk, int E) {
    int e = blockIdx.x * blockDim.x + threadIdx.x;
    if (e < E) {
        int p = atomicAdd(&cursor[dst[e]], 1);
        pk[p] = src[e] | (rid[e] << 20);
    }
}

// ---------------- layernorm (warp per row) ----------------
template<typename Tout>
__global__ void ln_kernel(const float* __restrict__ x, const float* __restrict__ g,
                          const float* __restrict__ b, Tout* __restrict__ y, int nrows) {
    int w = (blockIdx.x * blockDim.x + threadIdx.x) >> 5;
    if (w >= nrows) return;
    int lane = threadIdx.x & 31;
    float4 v = *(const float4*)(x + (long)w * D + lane * 4);
    float s = v.x + v.y + v.z + v.w;
    #pragma unroll
    for (int o = 16; o; o >>= 1) s += __shfl_xor_sync(0xffffffffu, s, o);
    float mean = s * (1.0f / 128.0f);
    float dx = v.x - mean, dy = v.y - mean, dz = v.z - mean, dw = v.w - mean;
    float q = dx * dx + dy * dy + dz * dz + dw * dw;
    #pragma unroll
    for (int o = 16; o; o >>= 1) q += __shfl_xor_sync(0xffffffffu, q, o);
    float inv = rsqrtf(q * (1.0f / 128.0f) + 1e-5f);
    float4 g4 = *(const float4*)(g + lane * 4);
    float4 b4 = *(const float4*)(b + lane * 4);
    st2(y + (long)w * D + lane * 4,     dx * inv * g4.x + b4.x, dy * inv * g4.y + b4.y);
    st2(y + (long)w * D + lane * 4 + 2, dz * inv * g4.z + b4.z, dw * inv * g4.w + b4.w);
}

// ---------------- single-shot fp16 GEMM, K=128 fixed ----------------
#define MS_STRIDE 136
#define MM1_SMEM ((128 * MS_STRIDE + 128 * 128) * 2)
template<typename Tout>
__global__ void __launch_bounds__(256, 2) mm1_f16_kernel(
    const __half* __restrict__ X, const __half* __restrict__ W,
    Tout* __restrict__ Y, int M, int Nc)
{
    extern __shared__ __half sm1[];
    __half* As = sm1;                    // 128 x 136
    __half* Bs = sm1 + 128 * MS_STRIDE;  // 128 x 128 swizzled
    const int tid = threadIdx.x;
    const int lane = tid & 31;
    const int warp = tid >> 5;
    const int m_off = (warp & 3) * 32;
    const int n_off = (warp >> 2) * 64;
    const int r0 = blockIdx.x * 128;
    const int n0 = blockIdx.y * 128;

    #pragma unroll
    for (int i = 0; i < 8; i++) {
        int ci = tid + i * 256;
        int r = ci >> 4, kc = (ci & 15) * 8;
        int gr = r0 + r;
        cp_async16(smem_u32(&As[r * MS_STRIDE + kc]), X + (long)gr * 128 + kc, gr < M);
        cp_async16(smem_u32(&Bs[BSW(r, kc)]), W + (long)r * Nc + n0 + kc, true);
    }
    asm volatile("cp.async.commit_group;\n" ::);

    float acc[2][8][4];
    #pragma unroll
    for (int mi = 0; mi < 2; mi++)
        #pragma unroll
        for (int ni = 0; ni < 8; ni++)
            #pragma unroll
            for (int j = 0; j < 4; j++) acc[mi][ni][j] = 0.0f;

    asm volatile("cp.async.wait_group 0;\n" ::);
    __syncthreads();

    #pragma unroll
    for (int ks = 0; ks < 8; ks++) {
        uint32_t a[2][4];
        #pragma unroll
        for (int mi = 0; mi < 2; mi++) {
            int m = m_off + mi * 16 + (lane & 7) + (lane & 8);
            int k = ks * 16 + ((lane >> 4) << 3);
            ldsm4(a[mi], smem_u32(&As[m * MS_STRIDE + k]));
        }
        uint32_t b[8][2];
        #pragma unroll
        for (int nb = 0; nb < 4; nb++) {
            uint32_t r[4];
            int k = ks * 16 + (lane & 7) + (lane & 8);
            int n = n_off + nb * 16 + ((lane >> 4) << 3);
            ldsm4t(r, smem_u32(&Bs[BSW(k, n)]));
            b[nb * 2][0] = r[0]; b[nb * 2][1] = r[1];
            b[nb * 2 + 1][0] = r[2]; b[nb * 2 + 1][1] = r[3];
        }
        #pragma unroll
        for (int mi = 0; mi < 2; mi++)
            #pragma unroll
            for (int ni = 0; ni < 8; ni++)
                mma_f16(acc[mi][ni], a[mi], b[ni]);
    }

    #pragma unroll
    for (int mi = 0; mi < 2; mi++) {
        #pragma unroll
        for (int half = 0; half < 2; half++) {
            int row = m_off + mi * 16 + (lane >> 2) + half * 8;
            int gr = r0 + row;
            if (gr >= M) continue;
            #pragma unroll
            for (int ni = 0; ni < 8; ni++) {
                int col = n_off + ni * 8 + (lane & 3) * 2;
                st2(Y + (long)gr * Nc + n0 + col,
                    acc[mi][ni][half * 2 + 0], acc[mi][ni][half * 2 + 1]);
            }
        }
    }
}

// ---------------- fused FFN: 128 threads, 64-row tile, 32x64 warp tiles ----------------
#define FS_STRIDE 136
#define FFN_SMEM ((2 * 64 * FS_STRIDE + 2 * 128 * 128) * 2)
__global__ void __launch_bounds__(128, 2) ffn_fused_kernel(
    const __half* __restrict__ Yh, const __half* __restrict__ W1,
    const __half* __restrict__ W2, const float* __restrict__ b1,
    const float* __restrict__ b2, const float* __restrict__ rst,
    float* __restrict__ out, int M)
{
    extern __shared__ __half fsm[];
    __half* As  = fsm;                                     // 64 x 136
    __half* Hs  = fsm + 64 * FS_STRIDE;                    // 64 x 136
    __half* Bs0 = fsm + 2 * 64 * FS_STRIDE;                // 128 x 128 swz
    __half* Bs1 = Bs0 + 128 * 128;                         // 128 x 128 swz
    const int tid = threadIdx.x;
    const int lane = tid & 31;
    const int warp = tid >> 5;             // 0..3
    const int m_off = (warp & 1) * 32;     // 2 x 2 grid of 32x64 warp tiles
    const int n_off = (warp >> 1) * 64;
    const int r0 = blockIdx.x * 64;

    auto load_w = [&](const __half* Wsrc, int row0, int col0, int ldw, __half* dstBs) {
        #pragma unroll
        for (int i = 0; i < 16; i++) {
            int ci = tid + i * 128;
            int r = ci >> 4, nc = (ci & 15) * 8;
            cp_async16(smem_u32(&dstBs[BSW(r, nc)]),
                       Wsrc + (long)(row0 + r) * ldw + col0 + nc, true);
        }
    };

    #pragma unroll
    for (int i = 0; i < 8; i++) {
        int ci = tid + i * 128;
        int r = ci >> 4, kc = (ci & 15) * 8;
        int gr = r0 + r;
        cp_async16(smem_u32(&As[r * FS_STRIDE + kc]), Yh + (long)gr * D + kc, gr < M);
    }
    load_w(W1, 0, 0, 512, Bs0);
    asm volatile("cp.async.commit_group;\n" ::);

    float acc2[2][8][4];
    #pragma unroll
    for (int mi = 0; mi < 2; mi++)
        #pragma unroll
        for (int ni = 0; ni < 8; ni++)
            #pragma unroll
            for (int j = 0; j < 4; j++) acc2[mi][ni][j] = 0.0f;

    auto gemm64 = [&](const __half* A, const __half* B, float acc[2][8][4]) {
        #pragma unroll
        for (int ks = 0; ks < 8; ks++) {
            uint32_t a[2][4];
            #pragma unroll
            for (int mi = 0; mi < 2; mi++) {
                int m = m_off + mi * 16 + (lane & 7) + (lane & 8);
                int k = ks * 16 + ((lane >> 4) << 3);
                ldsm4(a[mi], smem_u32(&A[m * FS_STRIDE + k]));
            }
            uint32_t b[8][2];
            #pragma unroll
            for (int nb = 0; nb < 4; nb++) {
                uint32_t r[4];
                int k = ks * 16 + (lane & 7) + (lane & 8);
                int n = n_off + nb * 16 + ((lane >> 4) << 3);
                ldsm4t(r, smem_u32(&B[BSW(k, n)]));
                b[nb * 2][0] = r[0]; b[nb * 2][1] = r[1];
                b[nb * 2 + 1][0] = r[2]; b[nb * 2 + 1][1] = r[3];
            }
            #pragma unroll
            for (int mi = 0; mi < 2; mi++)
                #pragma unroll
                for (int ni = 0; ni < 8; ni++)
                    mma_f16(acc[mi][ni], a[mi], b[ni]);
        }
    };

    for (int c = 0; c < 4; c++) {
        load_w(W2, c * 128, 0, 128, Bs1);
        asm volatile("cp.async.commit_group;\n" ::);
        asm volatile("cp.async.wait_group 1;\n" ::);
        __syncthreads();

        float accT[2][8][4];
        #pragma unroll
        for (int mi = 0; mi < 2; mi++)
            #pragma unroll
            for (int ni = 0; ni < 8; ni++)
                #pragma unroll
                for (int j = 0; j < 4; j++) accT[mi][ni][j] = 0.0f;
        gemm64(As, Bs0, accT);
        __syncthreads();

        if (c < 3) {
            load_w(W1, 0, (c + 1) * 128, 512, Bs0);
            asm volatile("cp.async.commit_group;\n" ::);
        }

        #pragma unroll
        for (int mi = 0; mi < 2; mi++) {
            #pragma unroll
            for (int half = 0; half < 2; half++) {
                int row = m_off + mi * 16 + (lane >> 2) + half * 8;
                #pragma unroll
                for (int ni = 0; ni < 8; ni++) {
                    int col = n_off + ni * 8 + (lane & 3) * 2;
                    float v0 = fmaxf(accT[mi][ni][half * 2 + 0] + b1[c * 128 + col], 0.0f);
                    float v1 = fmaxf(accT[mi][ni][half * 2 + 1] + b1[c * 128 + col + 1], 0.0f);
                    *(__half2*)(&Hs[row * FS_STRIDE + col]) = __floats2half2_rn(v0, v1);
                }
            }
        }
        if (c < 3) { asm volatile("cp.async.wait_group 1;\n" ::); }
        else       { asm volatile("cp.async.wait_group 0;\n" ::); }
        __syncthreads();

        gemm64(Hs, Bs1, acc2);
        __syncthreads();
    }

    #pragma unroll
    for (int mi = 0; mi < 2; mi++) {
        #pragma unroll
        for (int half = 0; half < 2; half++) {
            int row = m_off + mi * 16 + (lane >> 2) + half * 8;
            int gr = r0 + row;
            if (gr >= M) continue;
            #pragma unroll
            for (int ni = 0; ni < 8; ni++) {
                int col = n_off + ni * 8 + (lane & 3) * 2;
                float v0 = acc2[mi][ni][half * 2 + 0] + b2[col] + rst[(long)gr * D + col];
                float v1 = acc2[mi][ni][half * 2 + 1] + b2[col + 1] + rst[(long)gr * D + col + 1];
                st2(out + (long)gr * D + col, v0, v1);
            }
        }
    }
}

// ---------------- fused attention + hop1 (warp per dst node) ----------------
__global__ void attn_hop1_kernel(const int* __restrict__ rowoff, const int* __restrict__ deg,
                                 const int* __restrict__ pk,
                                 const __half* __restrict__ kqv,
                                 const __half* __restrict__ relp, __half* __restrict__ exh,
                                 float* __restrict__ nscale, __half* __restrict__ fA, int N) {
    int w = (blockIdx.x * blockDim.x + threadIdx.x) >> 5;
    if (w >= N) return;
    int lane = threadIdx.x & 31;
    int head4 = lane >> 2;
    int start = rowoff[w];
    int dg = deg[w];
    float4 q4 = ld4(kqv + (long)w * 384 + 128 + lane * 4);
    float c = log1pf((float)dg) * 0.25f;  // log_in / sqrt(DH)
    float sum = 0.0f;
    float4 acc = make_float4(0.f, 0.f, 0.f, 0.f);
    int i = 0;
    for (; i + 2 <= dg; i += 2) {
        int pk0 = pk[start + i], pk1 = pk[start + i + 1];
        long s0 = (long)(pk0 & SRCMASK) * 384, s1 = (long)(pk1 & SRCMASK) * 384;
        float4 k0 = ld4(kqv + s0 + lane * 4);
        float4 k1 = ld4(kqv + s1 + lane * 4);
        float4 r0 = ld4(relp + (long)(pk0 >> 20) * D + lane * 4);
        float4 r1 = ld4(relp + (long)(pk1 >> 20) * D + lane * 4);
        float p0 = k0.x * r0.x * q4.x + k0.y * r0.y * q4.y + k0.z * r0.z * q4.z + k0.w * r0.w * q4.w;
        float p1 = k1.x * r1.x * q4.x + k1.y * r1.y * q4.y + k1.z * r1.z * q4.z + k1.w * r1.w * q4.w;
        p0 += __shfl_xor_sync(0xffffffffu, p0, 1);
        p1 += __shfl_xor_sync(0xffffffffu, p1, 1);
        p0 += __shfl_xor_sync(0xffffffffu, p0, 2);
        p1 += __shfl_xor_sync(0xffffffffu, p1, 2);
        float e0 = __expf(p0 * c);   // logits tiny: no max-subtraction needed
        float e1 = __expf(p1 * c);
        if ((lane & 3) == 0) {
            exh[(long)(start + i) * H + head4] = __float2half(e0);
            exh[(long)(start + i + 1) * H + head4] = __float2half(e1);
        }
        float4 v0 = ld4(kqv + s0 + 256 + lane * 4);
        float4 v1 = ld4(kqv + s1 + 256 + lane * 4);
        acc.x += e0 * v0.x + e1 * v1.x;
        acc.y += e0 * v0.y + e1 * v1.y;
        acc.z += e0 * v0.z + e1 * v1.z;
        acc.w += e0 * v0.w + e1 * v1.w;
        sum += e0 + e1;
    }
    if (i < dg) {
        int pk0 = pk[start + i];
        long s0 = (long)(pk0 & SRCMASK) * 384;
        float4 k0 = ld4(kqv + s0 + lane * 4);
        float4 r0 = ld4(relp + (long)(pk0 >> 20) * D + lane * 4);
        float p0 = k0.x * r0.x * q4.x + k0.y * r0.y * q4.y + k0.z * r0.z * q4.z + k0.w * r0.w * q4.w;
        p0 += __shfl_xor_sync(0xffffffffu, p0, 1);
        p0 += __shfl_xor_sync(0xffffffffu, p0, 2);
        float e0 = __expf(p0 * c);
        if ((lane & 3) == 0) exh[(long)(start + i) * H + head4] = __float2half(e0);
        float4 v0 = ld4(kqv + s0 + 256 + lane * 4);
        acc.x += e0 * v0.x;
        acc.y += e0 * v0.y;
        acc.z += e0 * v0.z;
        acc.w += e0 * v0.w;
        sum += e0;
    }
    float sc = (sum > 0.0f) ? ((1.0f - ALPHA) / sum) : 0.0f;
    float4 z = ld4(kqv + (long)w * 384 + 256 + lane * 4);
    acc.x = acc.x * sc + ALPHA * z.x;
    acc.y = acc.y * sc + ALPHA * z.y;
    acc.z = acc.z * sc + ALPHA * z.z;
    acc.w = acc.w * sc + ALPHA * z.w;
    float2 pkd;
    ((__half2*)&pkd)[0] = __floats2half2_rn(acc.x, acc.y);
    ((__half2*)&pkd)[1] = __floats2half2_rn(acc.z, acc.w);
    *(float2*)(fA + (long)w * D + lane * 4) = pkd;
    float s_h = __shfl_sync(0xffffffffu, sum, (lane & 7) * 4);
    if (lane < 8)
        nscale[(long)w * H + lane] = (s_h > 0.0f) ? ((1.0f - ALPHA) / s_h) : 0.0f;
}

// ---------------- PPR diffusion hop (warp per dst node, unroll-2) ----------------
__global__ void hop_kernel(const int* __restrict__ rowoff, const int* __restrict__ deg,
                           const int* __restrict__ pk, const __half* __restrict__ exh,
                           const float* __restrict__ nscale,
                           const __half* __restrict__ fin,
                           const __half* __restrict__ f0,
                           __half* __restrict__ fout, int N) {
    int w = (blockIdx.x * blockDim.x + threadIdx.x) >> 5;
    if (w >= N) return;
    int lane = threadIdx.x & 31;
    int head = lane >> 2;
    int start = rowoff[w];
    int dg = deg[w];
    float4 acc = make_float4(0.f, 0.f, 0.f, 0.f);
    int i = 0;
    for (; i + 2 <= dg; i += 2) {
        int pk0 = pk[start + i], pk1 = pk[start + i + 1];
        float e0 = __half2float(exh[(long)(start + i) * H + head]);
        float e1 = __half2float(exh[(long)(start + i + 1) * H + head]);
        float4 fa = ld4(fin + (long)(pk0 & SRCMASK) * D + lane * 4);
        float4 fb = ld4(fin + (long)(pk1 & SRCMASK) * D + lane * 4);
        acc.x += e0 * fa.x + e1 * fb.x;
        acc.y += e0 * fa.y + e1 * fb.y;
        acc.z += e0 * fa.z + e1 * fb.z;
        acc.w += e0 * fa.w + e1 * fb.w;
    }
    if (i < dg) {
        int pk0 = pk[start + i];
        float e0 = __half2float(exh[(long)(start + i) * H + head]);
        float4 fa = ld4(fin + (long)(pk0 & SRCMASK) * D + lane * 4);
        acc.x += e0 * fa.x;
        acc.y += e0 * fa.y;
        acc.z += e0 * fa.z;
        acc.w += e0 * fa.w;
    }
    float sc = nscale[(long)w * H + head];
    float4 z = ld4(f0 + (long)w * 384 + lane * 4);   // v inside kqv
    acc.x = acc.x * sc + ALPHA * z.x;
    acc.y = acc.y * sc + ALPHA * z.y;
    acc.z = acc.z * sc + ALPHA * z.z;
    acc.w = acc.w * sc + ALPHA * z.w;
    float2 pkd;
    ((__half2*)&pkd)[0] = __floats2half2_rn(acc.x, acc.y);
    ((__half2*)&pkd)[1] = __floats2half2_rn(acc.z, acc.w);
    *(float2*)(fout + (long)w * D + lane * 4) = pkd;
}

// ---------------- last hop fused with residual + LN (unroll-2) ----------------
__global__ void hop_last_kernel(const int* __restrict__ rowoff, const int* __restrict__ deg,
                                const int* __restrict__ pk, const __half* __restrict__ exh,
                                const float* __restrict__ nscale,
                                const __half* __restrict__ fin, const __half* __restrict__ f0,
                                const float* __restrict__ ent,
                                const float* __restrict__ g, const float* __restrict__ b,
                                __half* __restrict__ y, float* __restrict__ rst, int N) {
    int w = (blockIdx.x * blockDim.x + threadIdx.x) >> 5;
    if (w >= N) return;
    int lane = threadIdx.x & 31;
    int head = lane >> 2;
    int start = rowoff[w];
    int dg = deg[w];
    float4 acc = make_float4(0.f, 0.f, 0.f, 0.f);
    int i = 0;
    for (; i + 2 <= dg; i += 2) {
        int pk0 = pk[start + i], pk1 = pk[start + i + 1];
        float e0 = __half2float(exh[(long)(start + i) * H + head]);
        float e1 = __half2float(exh[(long)(start + i + 1) * H + head]);
        float4 fa = ld4(fin + (long)(pk0 & SRCMASK) * D + lane * 4);
        float4 fb = ld4(fin + (long)(pk1 & SRCMASK) * D + lane * 4);
        acc.x += e0 * fa.x + e1 * fb.x;
        acc.y += e0 * fa.y + e1 * fb.y;
        acc.z += e0 * fa.z + e1 * fb.z;
        acc.w += e0 * fa.w + e1 * fb.w;
    }
    if (i < dg) {
        int pk0 = pk[start + i];
        float e0 = __half2float(exh[(long)(start + i) * H + head]);
        float4 fa = ld4(fin + (long)(pk0 & SRCMASK) * D + lane * 4);
        acc.x += e0 * fa.x;
        acc.y += e0 * fa.y;
        acc.z += e0 * fa.z;
        acc.w += e0 * fa.w;
    }
    float sc = nscale[(long)w * H + head];
    float4 z = ld4(f0 + (long)w * 384 + lane * 4);
    float4 e4 = *(const float4*)(ent + (long)w * D + lane * 4);
    float4 v;
    v.x = acc.x * sc + ALPHA * z.x + e4.x;
    v.y = acc.y * sc + ALPHA * z.y + e4.y;
    v.z = acc.z * sc + ALPHA * z.z + e4.z;
    v.w = acc.w * sc + ALPHA * z.w + e4.w;
    *(float4*)(rst + (long)w * D + lane * 4) = v;
    float s = v.x + v.y + v.z + v.w;
    #pragma unroll
    for (int o = 16; o; o >>= 1) s += __shfl_xor_sync(0xffffffffu, s, o);
    float mean = s * (1.0f / 128.0f);
    float dx = v.x - mean, dy = v.y - mean, dz = v.z - mean, dw = v.w - mean;
    float q = dx * dx + dy * dy + dz * dz + dw * dw;
    #pragma unroll
    for (int o = 16; o; o >>= 1) q += __shfl_xor_sync(0xffffffffu, q, o);
    float inv = rsqrtf(q * (1.0f / 128.0f) + 1e-5f);
    float4 g4 = *(const float4*)(g + lane * 4);
    float4 b4 = *(const float4*)(b + lane * 4);
    st2(y + (long)w * D + lane * 4,     dx * inv * g4.x + b4.x, dy * inv * g4.y + b4.y);
    st2(y + (long)w * D + lane * 4 + 2, dz * inv * g4.z + b4.z, dw * inv * g4.w + b4.w);
}

// ---------------- launch ----------------
extern "C" void kernel_launch(void* const* d_in, const int* in_sizes, int n_in,
                              void* d_out, int out_size) {
    const float* ent    = (const float*)d_in[0];
    const float* relf   = (const float*)d_in[1];
    const float* W_head = (const float*)d_in[2];
    const float* W_tail = (const float*)d_in[3];
    const float* W_ent  = (const float*)d_in[4];
    const float* W_rel  = (const float*)d_in[5];
    const float* g_ent  = (const float*)d_in[6];
    const float* b_ent  = (const float*)d_in[7];
    const float* g_rel  = (const float*)d_in[8];
    const float* b_rel  = (const float*)d_in[9];
    const float* g_ff   = (const float*)d_in[10];
    const float* b_ff   = (const float*)d_in[11];
    const float* W1     = (const float*)d_in[12];
    const float* b1     = (const float*)d_in[13];
    const float* W2     = (const float*)d_in[14];
    const float* b2     = (const float*)d_in[15];
    const int*   src    = (const int*)d_in[16];
    const int*   dst    = (const int*)d_in[17];
    const int*   rid    = (const int*)d_in[18];
    float* out = (float*)d_out;

    int N = in_sizes[0] / D;
    int R = in_sizes[1] / D;
    int E = in_sizes[16];

    float *p_rst, *p_nscale;
    __half *p_xnh, *p_kqv, *p_fA, *p_fB, *p_exh, *p_relxh, *p_relph, *p_w16;
    int *p_deg, *p_rowoff, *p_cursor, *p_pk, *p_bsums;
    cudaGetSymbolAddress((void**)&p_xnh, d_xnh);
    cudaGetSymbolAddress((void**)&p_kqv, d_kqv);
    cudaGetSymbolAddress((void**)&p_rst, d_rst);
    cudaGetSymbolAddress((void**)&p_fA, d_fA);
    cudaGetSymbolAddress((void**)&p_fB, d_fB);
    cudaGetSymbolAddress((void**)&p_exh, d_exh);
    cudaGetSymbolAddress((void**)&p_nscale, d_nscale);
    cudaGetSymbolAddress((void**)&p_relxh, d_relxh);
    cudaGetSymbolAddress((void**)&p_relph, d_relph);
    cudaGetSymbolAddress((void**)&p_w16, d_w16);
    cudaGetSymbolAddress((void**)&p_deg, d_deg);
    cudaGetSymbolAddress((void**)&p_rowoff, d_rowoff);
    cudaGetSymbolAddress((void**)&p_cursor, d_cursor);
    cudaGetSymbolAddress((void**)&p_pk, d_pk);
    cudaGetSymbolAddress((void**)&p_bsums, d_bsums);

    cudaFuncSetAttribute(ffn_fused_kernel,
                         cudaFuncAttributeMaxDynamicSharedMemorySize, FFN_SMEM);
    cudaFuncSetAttribute((const void*)mm1_f16_kernel<__half>,
                         cudaFuncAttributeMaxDynamicSharedMemorySize, MM1_SMEM);

    int nb = (N + 1023) / 1024;
    int mblocks = (N + 127) / 128;

    // fork: CSR + rel chain run on cudaStreamPerThread, parallel to kqv chain.
    // Events created fresh per call and intentionally leaked (few harness calls;
    // destroying mid-capture is illegal; DisableTiming events hold no device mem).
    cudaEvent_t ev_fork, ev_w, ev_join;
    cudaEventCreateWithFlags(&ev_fork, cudaEventDisableTiming);
    cudaEventCreateWithFlags(&ev_w, cudaEventDisableTiming);
    cudaEventCreateWithFlags(&ev_join, cudaEventDisableTiming);
    cudaStream_t s2 = cudaStreamPerThread;

    cudaEventRecord(ev_fork, 0);
    cudaStreamWaitEvent(s2, ev_fork, 0);

    // branch A (s2): CSR build
    cudaMemsetAsync(p_deg, 0, N * sizeof(int), s2);
    hist_kernel<<<(E + 255) / 256, 256, 0, s2>>>(dst, p_deg, E);
    scan1_kernel<<<nb, 1024, 0, s2>>>(p_deg, p_rowoff, p_bsums, N);
    scan2_kernel<<<1, 256, 0, s2>>>(p_bsums, nb);
    scan3_kernel<<<(N + 255) / 256, 256, 0, s2>>>(p_rowoff, p_cursor, p_bsums, N);
    scatter_kernel<<<(E + 255) / 256, 256, 0, s2>>>(src, dst, rid, p_cursor, p_pk, E);

    // branch B (main): weights + LN + kqv projection
    cvt_weights<<<192, 256>>>(W_head, W_tail, W_ent, W_rel, W1, W2, p_w16);
    cudaEventRecord(ev_w, 0);
    ln_kernel<__half><<<(N + 7) / 8, 256>>>(ent, g_ent, b_ent, p_xnh, N);
    mm1_f16_kernel<__half><<<dim3(mblocks, 3), 256, MM1_SMEM>>>(
        p_xnh, p_w16 + OFF_WKQV, p_kqv, N, 384);

    // branch A continues: rel chain (needs w16 from branch B)
    cudaStreamWaitEvent(s2, ev_w, 0);
    ln_kernel<__half><<<(R + 7) / 8, 256, 0, s2>>>(relf, g_rel, b_rel, p_relxh, R);
    mm1_f16_kernel<__half><<<dim3(1, 1), 256, MM1_SMEM, s2>>>(
        p_relxh, p_w16 + OFF_WR, p_relph, R, 128);
    cudaEventRecord(ev_join, s2);

    // join: attention needs both branches
    cudaStreamWaitEvent(0, ev_join, 0);

    // fused attention + hop1
    attn_hop1_kernel<<<(N + 7) / 8, 256>>>(p_rowoff, p_deg, p_pk, p_kqv,
                                           p_relph, p_exh, p_nscale, p_fA, N);

    // hops 2,3 then last fused with residual+LN
    hop_kernel<<<(N + 7) / 8, 256>>>(p_rowoff, p_deg, p_pk, p_exh, p_nscale,
                                     p_fA, p_kqv + 256, p_fB, N);
    hop_kernel<<<(N + 7) / 8, 256>>>(p_rowoff, p_deg, p_pk, p_exh, p_nscale,
                                     p_fB, p_kqv + 256, p_fA, N);
    hop_last_kernel<<<(N + 7) / 8, 256>>>(p_rowoff, p_deg, p_pk, p_exh, p_nscale,
                                          p_fA, p_kqv + 256, ent, g_ff, b_ff,
                                          p_xnh, p_rst, N);   // y -> d_xnh

    // fused FFN (128 threads, 64-row tile, 32x64 warp tiles, 2 blocks/SM)
    ffn_fused_kernel<<<(N + 63) / 64, 128, FFN_SMEM>>>(
        p_xnh, p_w16 + OFF_W1, p_w16 + OFF_W2, b1, b2, p_rst, out, N);
}